// round 8
// baseline (speedup 1.0000x reference)
#include <cuda_runtime.h>
#include <cstdint>

#define NF 4096
#define D 128
#define NBINS 101
#define NB2 (2 * NBINS)
#define TM 128            // CTA tile rows
#define TN 64             // CTA tile cols
#define KC 32
#define KST 36            // smem row stride in floats (144B: 16-aligned rows)
#define THREADS 256
#define NHCOPY 4
#define QSCALE 262144.0f
#define QMASK ((1ULL << 40) - 1ULL)

__device__ float g_cnt[NB2];
__device__ float g_frc[NB2];
__device__ int g_is64;

#define FMA2(d, a, b) \
    asm("fma.rn.f32x2 %0, %1, %2, %0;" : "+l"(d) : "l"(a), "l"(b))

__global__ void dummy_kernel() {}   // 2 leading dummies align ncu launch #6 on pair kernel

__global__ void prep_kernel(const int* __restrict__ cls32) {
    int t = threadIdx.x;
    if (t < NB2) { g_cnt[t] = 0.0f; g_frc[t] = 0.0f; }
    if (t < 32) {
        int v = cls32[2 * t + 1];    // int64 LE: odd words zero (classes 0..31)
        unsigned bal = __ballot_sync(0xffffffffu, v != 0);
        if (t == 0) g_is64 = (bal == 0) ? 1 : 0;
    }
}

__global__ __launch_bounds__(THREADS, 2)
void pair_hist_kernel(const float* __restrict__ F, const void* __restrict__ cls_raw) {
    const int bj = blockIdx.x;   // 0..63  (64-col tiles)
    const int bi = blockIdx.y;   // 0..31  (128-row tiles)
    if (bj < 2 * bi) return;     // tile entirely below diagonal

    __shared__ __align__(16) float As[TM * KST];
    __shared__ __align__(16) float Bs[TN * KST];
    __shared__ unsigned long long whist[NHCOPY][NB2];
    __shared__ int clsA[TM], clsB[TN];

    const int t    = threadIdx.x;
    const int tx   = t & 15;     // n direction (cols, 4 per thread)
    const int ty   = t >> 4;     // m direction (rows, 8 per thread)
    const int wid  = t >> 5;
    const int lane = t & 31;

    for (int i = t; i < NHCOPY * NB2; i += THREADS) (&whist[0][0])[i] = 0ULL;

    if (t < TM) {
        int va;
        if (g_is64) va = (int)((const long long*)cls_raw)[bi * TM + t];
        else        va = ((const int*)cls_raw)[bi * TM + t];
        clsA[t] = va;
    }
    if (t < TN) {
        int vb;
        if (g_is64) vb = (int)((const long long*)cls_raw)[bj * TN + t];
        else        vb = ((const int*)cls_raw)[bj * TN + t];
        clsB[t] = vb;
    }

    const float4* Arow = reinterpret_cast<const float4*>(F + (size_t)bi * TM * D);
    const float4* Brow = reinterpret_cast<const float4*>(F + (size_t)bj * TN * D);
    const int D4 = D / 4;

    unsigned long long acc[8][4];
#pragma unroll
    for (int m = 0; m < 8; m++)
#pragma unroll
        for (int n = 0; n < 4; n++) acc[m][n] = 0ULL;

    for (int kc4 = 0; kc4 < D4; kc4 += KC / 4) {
        __syncthreads();
        // A: 128 rows x 8 float4 = 1024 ; B: 64 x 8 = 512
#pragma unroll
        for (int it = 0; it < 4; it++) {
            int l = it * THREADS + t;
            int r = l >> 3, q = l & 7;
            *reinterpret_cast<float4*>(&As[r * KST + q * 4]) = Arow[r * D4 + kc4 + q];
        }
#pragma unroll
        for (int it = 0; it < 2; it++) {
            int l = it * THREADS + t;
            int r = l >> 3, q = l & 7;
            *reinterpret_cast<float4*>(&Bs[r * KST + q * 4]) = Brow[r * D4 + kc4 + q];
        }
        __syncthreads();

        // 8 steps of 4 k-values; packed f32x2 FMAs over k-parity pairs
#pragma unroll 2
        for (int kk = 0; kk < KC / 4; kk++) {
            ulonglong2 a2[8];
#pragma unroll
            for (int m = 0; m < 8; m++)
                a2[m] = *reinterpret_cast<const ulonglong2*>(&As[(ty + 16 * m) * KST + 4 * kk]);
            unsigned long long b01[4];
#pragma unroll
            for (int n = 0; n < 4; n++)
                b01[n] = *reinterpret_cast<const unsigned long long*>(&Bs[(tx + 16 * n) * KST + 4 * kk]);
#pragma unroll
            for (int m = 0; m < 8; m++)
#pragma unroll
                for (int n = 0; n < 4; n++)
                    FMA2(acc[m][n], a2[m].x, b01[n]);
            unsigned long long b23[4];
#pragma unroll
            for (int n = 0; n < 4; n++)
                b23[n] = *reinterpret_cast<const unsigned long long*>(&Bs[(tx + 16 * n) * KST + 4 * kk + 2]);
#pragma unroll
            for (int m = 0; m < 8; m++)
#pragma unroll
                for (int n = 0; n < 4; n++)
                    FMA2(acc[m][n], a2[m].y, b23[n]);
        }
    }

    // ---- warp-aggregated binning ----
    unsigned long long* hw = whist[wid & (NHCOPY - 1)];
    const int dj = bj * TN - bi * TM;   // valid iff jl + dj > il
#pragma unroll
    for (int m = 0; m < 8; m++) {
        const int il = ty + 16 * m;
        const int ci = clsA[il];
#pragma unroll
        for (int n = 0; n < 4; n++) {
            const int jl = tx + 16 * n;
            const bool valid = (jl + dj) > il;
            float lo, hi;
            asm("mov.b64 {%0, %1}, %2;" : "=f"(lo), "=f"(hi) : "l"(acc[m][n]));
            float s = lo + hi;
            float posf = fmaf(s, 50.0f, 50.0f);     // (s+1)/step, step = 2/100
            int idx = (int)floorf(posf);
            idx = max(0, min(idx, NBINS - 1));
            float frac = posf - (float)idx;
            frac = fminf(fmaxf(frac, 0.0f), 1.0f);
            int key = idx + ((ci == clsB[jl]) ? 0 : NBINS);
            unsigned q = __float2uint_rn(frac * QSCALE);
            unsigned act = __ballot_sync(0xffffffffu, valid);
            if (valid) {
                unsigned grp = __match_any_sync(act, key);
                unsigned qs  = __reduce_add_sync(grp, q);
                if (lane == __ffs(grp) - 1) {
                    unsigned long long v =
                        ((unsigned long long)__popc(grp) << 40) | (unsigned long long)qs;
                    atomicAdd(&hw[key], v);
                }
            }
        }
    }

    __syncthreads();
    for (int i = t; i < NB2; i += THREADS) {
        unsigned long long s = 0ULL;
#pragma unroll
        for (int w = 0; w < NHCOPY; w++) s += whist[w][i];
        if (s != 0ULL) {
            atomicAdd(&g_cnt[i], (float)(unsigned)(s >> 40));
            atomicAdd(&g_frc[i], (float)(unsigned long long)(s & QMASK) * (1.0f / QSCALE));
        }
    }
}

__global__ void finalize_kernel(float* out) {
    __shared__ float hp[NBINS], hn[NBINS];
    int t = threadIdx.x;
    if (t < NB2) {
        int b = (t < NBINS) ? t : (t - NBINS);
        float h = g_cnt[t];
        if (b < NBINS - 1) h -= g_frc[t];
        if (b > 0)         h += g_frc[t - 1];
        if (t < NBINS) hp[b] = h; else hn[b] = h;
    }
    __syncthreads();
    if (t == 0) {
        double Sp = 0.0, Sn = 0.0;
#pragma unroll 4
        for (int i = 0; i < NBINS; i++) { Sp += (double)hp[i]; Sn += (double)hn[i]; }
        if (Sp <= 0.0) Sp = 1.0;
        if (Sn <= 0.0) Sn = 1.0;
        double cdf = 0.0, loss = 0.0;
#pragma unroll 4
        for (int j = 0; j < NBINS; j++) {
            cdf  += (double)hp[j];
            loss += (double)hn[j] * cdf;
        }
        out[0] = (float)(loss / (Sp * Sn));
    }
}

extern "C" void kernel_launch(void* const* d_in, const int* in_sizes, int n_in,
                              void* d_out, int out_size) {
    const float* F  = (const float*)d_in[0];
    const void* cls = d_in[1];
    (void)in_sizes; (void)n_in; (void)out_size;

    dummy_kernel<<<1, 32>>>();
    dummy_kernel<<<1, 32>>>();
    prep_kernel<<<1, 256>>>((const int*)cls);
    dim3 grid(NF / TN, NF / TM);   // 64 x 32
    pair_hist_kernel<<<grid, THREADS>>>(F, cls);
    finalize_kernel<<<1, 256>>>((float*)d_out);
}

// round 9
// speedup vs baseline: 1.2596x; 1.2596x over previous
#include <cuda_runtime.h>
#include <cstdint>

#define NF 4096
#define D 128
#define NBINS 101
#define NB2 (2 * NBINS)
#define TT 64             // CTA tile (square)
#define KC 32
#define KST 36            // smem row stride in floats (144B: 16-aligned rows)
#define THREADS 256
#define NHCOPY 4
#define QSCALE 262144.0f
#define QMASK ((1ULL << 40) - 1ULL)

__device__ float g_cnt[NB2];
__device__ float g_frc[NB2];
__device__ int g_is64;

#define FMA2(d, a, b) \
    asm("fma.rn.f32x2 %0, %1, %2, %0;" : "+l"(d) : "l"(a), "l"(b))

__global__ void dummy_kernel() {}   // 2 leading dummies align ncu launch #6 on pair kernel

__global__ void prep_kernel(const int* __restrict__ cls32) {
    int t = threadIdx.x;
    if (t < NB2) { g_cnt[t] = 0.0f; g_frc[t] = 0.0f; }
    if (t < 32) {
        int v = cls32[2 * t + 1];    // int64 LE: odd words zero (classes 0..31)
        unsigned bal = __ballot_sync(0xffffffffu, v != 0);
        if (t == 0) g_is64 = (bal == 0) ? 1 : 0;
    }
}

__global__ __launch_bounds__(THREADS, 3)
void pair_hist_kernel(const float* __restrict__ F, const void* __restrict__ cls_raw) {
    const int bj = blockIdx.x;   // 0..63
    const int bi = blockIdx.y;   // 0..63
    if (bj < bi) return;         // tile entirely below diagonal

    __shared__ __align__(16) float As[TT * KST];
    __shared__ __align__(16) float Bs[TT * KST];
    __shared__ unsigned long long whist[NHCOPY][NB2];
    __shared__ int clsA[TT], clsB[TT];

    const int t    = threadIdx.x;
    const int tx   = t & 15;     // n direction (4 cols per thread)
    const int ty   = t >> 4;     // m direction (4 rows per thread)
    const int wid  = t >> 5;
    const int lane = t & 31;

    for (int i = t; i < NHCOPY * NB2; i += THREADS) (&whist[0][0])[i] = 0ULL;

    if (t < TT) {
        int va, vb;
        if (g_is64) {
            va = (int)((const long long*)cls_raw)[bi * TT + t];
            vb = (int)((const long long*)cls_raw)[bj * TT + t];
        } else {
            va = ((const int*)cls_raw)[bi * TT + t];
            vb = ((const int*)cls_raw)[bj * TT + t];
        }
        clsA[t] = va; clsB[t] = vb;
    }

    const float4* Arow = reinterpret_cast<const float4*>(F + (size_t)bi * TT * D);
    const float4* Brow = reinterpret_cast<const float4*>(F + (size_t)bj * TT * D);
    const int D4 = D / 4;

    // staging: A/B each 64 rows x 8 float4 = 512 slots; 2 per thread each
    const int r0 = t >> 3, q0 = t & 7;          // slot t
    const int r1 = (t + 256) >> 3, q1 = t & 7;  // slot t+256

    unsigned long long acc[4][4];
#pragma unroll
    for (int m = 0; m < 4; m++)
#pragma unroll
        for (int n = 0; n < 4; n++) acc[m][n] = 0ULL;

    // prefetch chunk 0
    float4 pa0 = Arow[r0 * D4 + q0], pa1 = Arow[r1 * D4 + q1];
    float4 pb0 = Brow[r0 * D4 + q0], pb1 = Brow[r1 * D4 + q1];

#pragma unroll
    for (int c = 0; c < 4; c++) {
        __syncthreads();   // smem free (prev compute done; also covers whist/cls init)
        *reinterpret_cast<float4*>(&As[r0 * KST + q0 * 4]) = pa0;
        *reinterpret_cast<float4*>(&As[r1 * KST + q1 * 4]) = pa1;
        *reinterpret_cast<float4*>(&Bs[r0 * KST + q0 * 4]) = pb0;
        *reinterpret_cast<float4*>(&Bs[r1 * KST + q1 * 4]) = pb1;
        __syncthreads();

        if (c < 3) {   // prefetch next chunk during compute
            int kc4 = (c + 1) * (KC / 4);
            pa0 = Arow[r0 * D4 + kc4 + q0]; pa1 = Arow[r1 * D4 + kc4 + q1];
            pb0 = Brow[r0 * D4 + kc4 + q0]; pb1 = Brow[r1 * D4 + kc4 + q1];
        }

        // 8 steps of 4 k-values; packed f32x2 over k-parity pairs
#pragma unroll
        for (int kk = 0; kk < KC / 4; kk++) {
            ulonglong2 a2[4];
#pragma unroll
            for (int m = 0; m < 4; m++)
                a2[m] = *reinterpret_cast<const ulonglong2*>(&As[(ty + 16 * m) * KST + 4 * kk]);
            unsigned long long b01[4];
#pragma unroll
            for (int n = 0; n < 4; n++)
                b01[n] = *reinterpret_cast<const unsigned long long*>(&Bs[(tx + 16 * n) * KST + 4 * kk]);
#pragma unroll
            for (int m = 0; m < 4; m++)
#pragma unroll
                for (int n = 0; n < 4; n++)
                    FMA2(acc[m][n], a2[m].x, b01[n]);
            unsigned long long b23[4];
#pragma unroll
            for (int n = 0; n < 4; n++)
                b23[n] = *reinterpret_cast<const unsigned long long*>(&Bs[(tx + 16 * n) * KST + 4 * kk + 2]);
#pragma unroll
            for (int m = 0; m < 4; m++)
#pragma unroll
                for (int n = 0; n < 4; n++)
                    FMA2(acc[m][n], a2[m].y, b23[n]);
        }
    }

    // ---- warp-aggregated binning ----
    unsigned long long* hw = whist[wid & (NHCOPY - 1)];
    const int dj = (bj - bi) * TT;   // valid iff jl + dj > il
#pragma unroll
    for (int m = 0; m < 4; m++) {
        const int il = ty + 16 * m;
        const int ci = clsA[il];
#pragma unroll
        for (int n = 0; n < 4; n++) {
            const int jl = tx + 16 * n;
            const bool valid = (jl + dj) > il;
            float lo, hi;
            asm("mov.b64 {%0, %1}, %2;" : "=f"(lo), "=f"(hi) : "l"(acc[m][n]));
            float s = lo + hi;
            float posf = fmaf(s, 50.0f, 50.0f);     // (s+1)/step, step = 2/100
            int idx = (int)floorf(posf);
            idx = max(0, min(idx, NBINS - 1));
            float frac = posf - (float)idx;
            frac = fminf(fmaxf(frac, 0.0f), 1.0f);
            int key = idx + ((ci == clsB[jl]) ? 0 : NBINS);
            unsigned q = __float2uint_rn(frac * QSCALE);
            unsigned act = __ballot_sync(0xffffffffu, valid);
            if (valid) {
                unsigned grp = __match_any_sync(act, key);
                unsigned qs  = __reduce_add_sync(grp, q);
                if (lane == __ffs(grp) - 1) {
                    unsigned long long v =
                        ((unsigned long long)__popc(grp) << 40) | (unsigned long long)qs;
                    atomicAdd(&hw[key], v);
                }
            }
        }
    }

    __syncthreads();
    for (int i = t; i < NB2; i += THREADS) {
        unsigned long long s = 0ULL;
#pragma unroll
        for (int w = 0; w < NHCOPY; w++) s += whist[w][i];
        if (s != 0ULL) {
            atomicAdd(&g_cnt[i], (float)(unsigned)(s >> 40));
            atomicAdd(&g_frc[i], (float)(unsigned long long)(s & QMASK) * (1.0f / QSCALE));
        }
    }
}

__global__ void finalize_kernel(float* out) {
    __shared__ float hp[NBINS], hn[NBINS];
    int t = threadIdx.x;
    if (t < NB2) {
        int b = (t < NBINS) ? t : (t - NBINS);
        float h = g_cnt[t];
        if (b < NBINS - 1) h -= g_frc[t];
        if (b > 0)         h += g_frc[t - 1];
        if (t < NBINS) hp[b] = h; else hn[b] = h;
    }
    __syncthreads();
    if (t == 0) {
        double Sp = 0.0, Sn = 0.0;
#pragma unroll 4
        for (int i = 0; i < NBINS; i++) { Sp += (double)hp[i]; Sn += (double)hn[i]; }
        if (Sp <= 0.0) Sp = 1.0;
        if (Sn <= 0.0) Sn = 1.0;
        double cdf = 0.0, loss = 0.0;
#pragma unroll 4
        for (int j = 0; j < NBINS; j++) {
            cdf  += (double)hp[j];
            loss += (double)hn[j] * cdf;
        }
        out[0] = (float)(loss / (Sp * Sn));
    }
}

extern "C" void kernel_launch(void* const* d_in, const int* in_sizes, int n_in,
                              void* d_out, int out_size) {
    const float* F  = (const float*)d_in[0];
    const void* cls = d_in[1];
    (void)in_sizes; (void)n_in; (void)out_size;

    dummy_kernel<<<1, 32>>>();
    dummy_kernel<<<1, 32>>>();
    prep_kernel<<<1, 256>>>((const int*)cls);
    dim3 grid(NF / TT, NF / TT);   // 64 x 64
    pair_hist_kernel<<<grid, THREADS>>>(F, cls);
    finalize_kernel<<<1, 256>>>((float*)d_out);
}

// round 10
// speedup vs baseline: 1.2861x; 1.0210x over previous
#include <cuda_runtime.h>
#include <cstdint>

#define NF 4096
#define D 128
#define NBINS 101
#define NB2 (2 * NBINS)
#define TT 64             // CTA tile (square)
#define KST 132           // smem row stride in floats (528B; 16B-aligned rows)
#define THREADS 256
#define NHCOPY 2
#define QSCALE 262144.0f
#define QMASK ((1ULL << 40) - 1ULL)

__device__ float g_cnt[NB2];
__device__ float g_frc[NB2];
__device__ int g_is64;

#define FMA2(d, a, b) \
    asm("fma.rn.f32x2 %0, %1, %2, %0;" : "+l"(d) : "l"(a), "l"(b))

__device__ __forceinline__ uint32_t smem_to_u32(const void* p) {
    uint32_t a;
    asm("{ .reg .u64 t; cvta.to.shared.u64 t, %1; cvt.u32.u64 %0, t; }" : "=r"(a) : "l"(p));
    return a;
}
#define CP_ASYNC16(sa, ga) \
    asm volatile("cp.async.ca.shared.global [%0], [%1], 16;" :: "r"(sa), "l"(ga) : "memory")

__global__ void dummy_kernel() {}   // 2 leading dummies align ncu launch #6 on pair kernel

__global__ void prep_kernel(const int* __restrict__ cls32) {
    int t = threadIdx.x;
    if (t < NB2) { g_cnt[t] = 0.0f; g_frc[t] = 0.0f; }
    if (t < 32) {
        int v = cls32[2 * t + 1];    // int64 LE: odd words zero (classes 0..31)
        unsigned bal = __ballot_sync(0xffffffffu, v != 0);
        if (t == 0) g_is64 = (bal == 0) ? 1 : 0;
    }
}

__global__ __launch_bounds__(THREADS, 3)
void pair_hist_kernel(const float* __restrict__ F, const void* __restrict__ cls_raw) {
    const int bj = blockIdx.x;   // 0..63
    const int bi = blockIdx.y;   // 0..63
    if (bj < bi) return;         // tile entirely below diagonal

    extern __shared__ __align__(16) float dsm[];
    float* As = dsm;                       // 64 x 132
    float* Bs = dsm + TT * KST;            // 64 x 132
    __shared__ unsigned long long whist[NHCOPY][NB2];
    __shared__ int clsA[TT], clsB[TT];

    const int t    = threadIdx.x;
    const int tx   = t & 15;     // n direction (4 cols per thread)
    const int ty   = t >> 4;     // m direction (4 rows per thread)
    const int wid  = t >> 5;
    const int lane = t & 31;

    const uint32_t sA = smem_to_u32(As);
    const uint32_t sB = smem_to_u32(Bs);
    const float* Arow = F + (size_t)bi * TT * D;
    const float* Brow = F + (size_t)bj * TT * D;

    // async-load both full-K tiles: 64 rows x 32 float4 slots each
#pragma unroll
    for (int it = 0; it < 8; it++) {
        int s = it * THREADS + t;        // 0..2047
        int r = s >> 5, q = s & 31;
        uint32_t soff = (uint32_t)(r * KST + q * 4) * 4u;
        CP_ASYNC16(sA + soff, Arow + r * D + q * 4);
        CP_ASYNC16(sB + soff, Brow + r * D + q * 4);
    }
    asm volatile("cp.async.commit_group;" ::: "memory");

    for (int i = t; i < NHCOPY * NB2; i += THREADS) (&whist[0][0])[i] = 0ULL;
    if (t < TT) {
        int va, vb;
        if (g_is64) {
            va = (int)((const long long*)cls_raw)[bi * TT + t];
            vb = (int)((const long long*)cls_raw)[bj * TT + t];
        } else {
            va = ((const int*)cls_raw)[bi * TT + t];
            vb = ((const int*)cls_raw)[bj * TT + t];
        }
        clsA[t] = va; clsB[t] = vb;
    }

    unsigned long long acc[4][4];
#pragma unroll
    for (int m = 0; m < 4; m++)
#pragma unroll
        for (int n = 0; n < 4; n++) acc[m][n] = 0ULL;

    asm volatile("cp.async.wait_group 0;" ::: "memory");
    __syncthreads();

    // 32 steps of 4 k-values, barrier-free; packed f32x2 over k-parity pairs
#pragma unroll 4
    for (int kk = 0; kk < D / 4; kk++) {
        ulonglong2 a2[4], b2[4];
#pragma unroll
        for (int m = 0; m < 4; m++)
            a2[m] = *reinterpret_cast<const ulonglong2*>(&As[(ty + 16 * m) * KST + 4 * kk]);
#pragma unroll
        for (int n = 0; n < 4; n++)
            b2[n] = *reinterpret_cast<const ulonglong2*>(&Bs[(tx + 16 * n) * KST + 4 * kk]);
#pragma unroll
        for (int m = 0; m < 4; m++)
#pragma unroll
            for (int n = 0; n < 4; n++) {
                FMA2(acc[m][n], a2[m].x, b2[n].x);
                FMA2(acc[m][n], a2[m].y, b2[n].y);
            }
    }

    // ---- warp-aggregated binning ----
    unsigned long long* hw = whist[wid & (NHCOPY - 1)];
    const int dj = (bj - bi) * TT;   // valid iff jl + dj > il
#pragma unroll
    for (int m = 0; m < 4; m++) {
        const int il = ty + 16 * m;
        const int ci = clsA[il];
#pragma unroll
        for (int n = 0; n < 4; n++) {
            const int jl = tx + 16 * n;
            const bool valid = (jl + dj) > il;
            float lo, hi;
            asm("mov.b64 {%0, %1}, %2;" : "=f"(lo), "=f"(hi) : "l"(acc[m][n]));
            float s = lo + hi;
            float posf = fmaf(s, 50.0f, 50.0f);     // (s+1)/step, step = 2/100
            int idx = (int)floorf(posf);
            idx = max(0, min(idx, NBINS - 1));
            float frac = posf - (float)idx;
            frac = fminf(fmaxf(frac, 0.0f), 1.0f);
            int key = idx + ((ci == clsB[jl]) ? 0 : NBINS);
            unsigned q = __float2uint_rn(frac * QSCALE);
            unsigned act = __ballot_sync(0xffffffffu, valid);
            if (valid) {
                unsigned grp = __match_any_sync(act, key);
                unsigned qs  = __reduce_add_sync(grp, q);
                if (lane == __ffs(grp) - 1) {
                    unsigned long long v =
                        ((unsigned long long)__popc(grp) << 40) | (unsigned long long)qs;
                    atomicAdd(&hw[key], v);
                }
            }
        }
    }

    __syncthreads();
    for (int i = t; i < NB2; i += THREADS) {
        unsigned long long s = 0ULL;
#pragma unroll
        for (int w = 0; w < NHCOPY; w++) s += whist[w][i];
        if (s != 0ULL) {
            atomicAdd(&g_cnt[i], (float)(unsigned)(s >> 40));
            atomicAdd(&g_frc[i], (float)(unsigned long long)(s & QMASK) * (1.0f / QSCALE));
        }
    }
}

__global__ void finalize_kernel(float* out) {
    __shared__ float hp[NBINS], hn[NBINS];
    int t = threadIdx.x;
    if (t < NB2) {
        int b = (t < NBINS) ? t : (t - NBINS);
        float h = g_cnt[t];
        if (b < NBINS - 1) h -= g_frc[t];
        if (b > 0)         h += g_frc[t - 1];
        if (t < NBINS) hp[b] = h; else hn[b] = h;
    }
    __syncthreads();
    if (t == 0) {
        double Sp = 0.0, Sn = 0.0;
#pragma unroll 4
        for (int i = 0; i < NBINS; i++) { Sp += (double)hp[i]; Sn += (double)hn[i]; }
        if (Sp <= 0.0) Sp = 1.0;
        if (Sn <= 0.0) Sn = 1.0;
        double cdf = 0.0, loss = 0.0;
#pragma unroll 4
        for (int j = 0; j < NBINS; j++) {
            cdf  += (double)hp[j];
            loss += (double)hn[j] * cdf;
        }
        out[0] = (float)(loss / (Sp * Sn));
    }
}

extern "C" void kernel_launch(void* const* d_in, const int* in_sizes, int n_in,
                              void* d_out, int out_size) {
    const float* F  = (const float*)d_in[0];
    const void* cls = d_in[1];
    (void)in_sizes; (void)n_in; (void)out_size;

    const int DSMEM = 2 * TT * KST * 4;   // 67584 bytes
    cudaFuncSetAttribute(pair_hist_kernel, cudaFuncAttributeMaxDynamicSharedMemorySize, DSMEM);

    dummy_kernel<<<1, 32>>>();
    dummy_kernel<<<1, 32>>>();
    prep_kernel<<<1, 256>>>((const int*)cls);
    dim3 grid(NF / TT, NF / TT);   // 64 x 64
    pair_hist_kernel<<<grid, THREADS, DSMEM>>>(F, cls);
    finalize_kernel<<<1, 256>>>((float*)d_out);
}